// round 12
// baseline (speedup 1.0000x reference)
#include <cuda_runtime.h>
#include <math.h>

#define NN 50000
#define NE 800000
#define ETOT 850000   // NE + NN self loops
#define NG 512
#define NBLK ((NN + 255) / 256)   // 196 scan blocks

static inline int cdiv(int a, int b){ return (a + b - 1) / b; }

// ---------------- scratch (device globals; no allocations allowed) ----------------
__device__ __align__(256) float g_xl [NN * 64];   // source transform
__device__ __align__(256) float g_xr [NN * 64];   // target transform
__device__ __align__(256) float g_h1 [NN * 64];   // layer1 output (ELU'd)
__device__ __align__(256) float g_pool[NG * 32];
__device__ __align__(256) float g_cnt [NG];
__device__ __align__(256) int   g_src [ETOT];     // int32 edge sources (incl self loops)
__device__ __align__(256) int   g_dst [ETOT];     // int32 edge destinations
__device__ __align__(256) int   g_batch[NN];      // int32 graph id per node
__device__ __align__(256) int   g_deg [NN];       // per-dst degree
__device__ __align__(256) int   g_rowptr[NN + 1]; // CSR row pointers (by dst)
__device__ __align__(256) int   g_cursor[NN];     // scatter cursors
__device__ __align__(256) int   g_csrc[ETOT];     // CSR-ordered source node ids
__device__ __align__(256) int   g_bsum[NBLK];     // per-block scan sums
__device__ __align__(256) int   g_boff[NBLK];     // exclusive block offsets
__device__ int g_idx64;                           // 1 if input indices are int64

// ---------------- packed f32x2 helpers (Blackwell; ptxas never auto-fuses) ----------
__device__ __forceinline__ unsigned long long ffma2(unsigned long long a,
                                                    unsigned long long b,
                                                    unsigned long long c){
    unsigned long long d;
    asm("fma.rn.f32x2 %0, %1, %2, %3;" : "=l"(d) : "l"(a), "l"(b), "l"(c));
    return d;
}
__device__ __forceinline__ unsigned long long pack2(float x, float y){
    unsigned long long d;
    asm("mov.b64 %0, {%1, %2};" : "=l"(d) : "f"(x), "f"(y));
    return d;
}
__device__ __forceinline__ void unpack2(unsigned long long v, float& x, float& y){
    asm("mov.b64 {%0, %1}, %2;" : "=f"(x), "=f"(y) : "l"(v));
}

// ---------------- zero pass + index dtype detection (fused) ----------------
__global__ void k_prep(const unsigned* __restrict__ eiraw){
    int t = blockIdx.x * blockDim.x + threadIdx.x;
    if (t < NN)      g_deg[t] = 0;
    if (t < NG * 32) g_pool[t] = 0.f;
    if (t < NG)      g_cnt[t]  = 0.f;
    if (t == 0){
        int is64 = 1;
        for (int i = 0; i < 128; i++){
            if (eiraw[2 * i + 1] != 0u) { is64 = 0; break; }
        }
        g_idx64 = is64;
    }
}

// ---------------- convert + histogram (fused single edge pass) ----------------
__global__ void k_convert(const void* __restrict__ ei, const void* __restrict__ batch){
    int t = blockIdx.x * blockDim.x + threadIdx.x;
    int is64 = g_idx64;
    if (t < ETOT){
        int s, d;
        if (t < NE){
            if (is64){
                s = (int)((const long long*)ei)[t];
                d = (int)((const long long*)ei)[NE + t];
            } else {
                s = ((const int*)ei)[t];
                d = ((const int*)ei)[NE + t];
            }
        } else { s = t - NE; d = s; }    // self loops appended
        s = min(max(s, 0), NN - 1);      // memory-safety clamp
        d = min(max(d, 0), NN - 1);
        g_src[t] = s; g_dst[t] = d;
        atomicAdd(&g_deg[d], 1);
    }
    if (t < NN){
        int b = is64 ? (int)((const long long*)batch)[t] : ((const int*)batch)[t];
        g_batch[t] = min(max(b, 0), NG - 1);
    }
}

// ---------------- multi-block exclusive scan of g_deg -> g_rowptr ----------------
__device__ __forceinline__ int blockScanIncl(int v, int tid, int* wsum){
    int x = v;
    #pragma unroll
    for (int o = 1; o < 32; o <<= 1){
        int y = __shfl_up_sync(0xFFFFFFFFu, x, o);
        if ((tid & 31) >= o) x += y;
    }
    if ((tid & 31) == 31) wsum[tid >> 5] = x;
    __syncthreads();
    if (tid < 8){
        int w = wsum[tid];
        #pragma unroll
        for (int o = 1; o < 8; o <<= 1){
            int y = __shfl_up_sync(0xFFu, w, o);
            if (tid >= o) w += y;
        }
        wsum[tid] = w;
    }
    __syncthreads();
    int base = (tid >= 32) ? wsum[(tid >> 5) - 1] : 0;
    return x + base;
}

__global__ void __launch_bounds__(256) k_scan1(){
    __shared__ int wsum[8];
    int tid = threadIdx.x, bid = blockIdx.x;
    int i = bid * 256 + tid;
    int v = (i < NN) ? g_deg[i] : 0;
    int incl = blockScanIncl(v, tid, wsum);
    if (i < NN) g_rowptr[i] = incl - v;         // exclusive within block
    if (tid == 255) g_bsum[bid] = incl;         // block total
}

__global__ void __launch_bounds__(256) k_scan2(){
    __shared__ int wsum[8];
    int tid = threadIdx.x;
    int v = (tid < NBLK) ? g_bsum[tid] : 0;
    int incl = blockScanIncl(v, tid, wsum);
    if (tid < NBLK) g_boff[tid] = incl - v;     // exclusive block offsets
}

__global__ void __launch_bounds__(256) k_scan3(){
    int i = blockIdx.x * 256 + threadIdx.x;
    if (i < NN){
        int val = g_rowptr[i] + g_boff[blockIdx.x];
        g_rowptr[i] = val;
        g_cursor[i] = val;
    }
    if (i == 0) g_rowptr[NN] = ETOT;            // total is statically known
}

__global__ void k_scatter(){
    int e = blockIdx.x * blockDim.x + threadIdx.x;
    if (e >= ETOT) return;
    int d = g_dst[e];
    int pos = atomicAdd(&g_cursor[d], 1);
    g_csrc[pos] = g_src[e];
}

// ---------------- linear: xl = X@Wl + bl ; xr = X@Wr  (fused as one GEMM, N=2D) ----
// BM=128, BN=64, BK=16, 256 threads, 8x4 register tile, double-buffered smem,
// inner product done with packed fma.rn.f32x2 (A row-pairs come pre-packed from
// the k-major transposed smem layout; only B needs dup-packs).
template<int K, int D>
__global__ void __launch_bounds__(256) k_lin(const float* __restrict__ Xin,
                                             const float* __restrict__ Wl,
                                             const float* __restrict__ bl,
                                             const float* __restrict__ Wr)
{
    const float* __restrict__ X = (K == 128) ? Xin : (const float*)g_h1;

    __shared__ float As[2][16][132];   // padded, stored transposed [k][m]
    __shared__ float Bs[2][16][64];

    const int tid = threadIdx.x;
    const int rowBase = blockIdx.x * 128;
    const int by = blockIdx.y;

    const int ra = tid >> 2, ka = (tid & 3) << 2;
    const int rb = tid >> 4, jb = (tid & 15) << 2;
    const int tx = tid & 15, ty = tid >> 4;

    const int jglob = by * 64 + jb;                 // virtual concat [Wl | Wr]
    const float* Wp = (jglob < D) ? Wl : Wr;
    const int jj = (jglob < D) ? jglob : (jglob - D);

    auto loadTile = [&](int k0, int buf){
        #pragma unroll
        for (int h = 0; h < 2; h++){
            int r = ra + h * 64;
            int gr = rowBase + r;
            float4 av = make_float4(0.f, 0.f, 0.f, 0.f);
            if (gr < NN) av = *(const float4*)&X[gr * K + k0 + ka];
            As[buf][ka + 0][r] = av.x; As[buf][ka + 1][r] = av.y;
            As[buf][ka + 2][r] = av.z; As[buf][ka + 3][r] = av.w;
        }
        float4 bv = *(const float4*)&Wp[(k0 + rb) * D + jj];
        *(float4*)&Bs[buf][rb][jb] = bv;
    };

    // acc as packed row-pairs: accp[r][j] = rows (2r, 2r+1), col j
    unsigned long long accp[4][4];
    #pragma unroll
    for (int r = 0; r < 4; r++)
        #pragma unroll
        for (int j = 0; j < 4; j++) accp[r][j] = 0ull;   // (0.f, 0.f)

    loadTile(0, 0);
    __syncthreads();

    int buf = 0;
    for (int k0 = 0; k0 < K; k0 += 16, buf ^= 1){
        if (k0 + 16 < K) loadTile(k0 + 16, buf ^ 1);   // overlap loads with compute

        #pragma unroll
        for (int kk = 0; kk < 16; kk++){
            // A row-pairs: 8 consecutive rows = 4 u64 pairs (pre-packed in smem)
            const ulonglong2* ap = (const ulonglong2*)&As[buf][kk][ty * 8];
            ulonglong2 p01 = ap[0], p23 = ap[1];
            unsigned long long apair[4] = {p01.x, p01.y, p23.x, p23.y};
            float4 b = *(const float4*)&Bs[buf][kk][tx * 4];
            unsigned long long bd[4] = {pack2(b.x, b.x), pack2(b.y, b.y),
                                        pack2(b.z, b.z), pack2(b.w, b.w)};
            #pragma unroll
            for (int r = 0; r < 4; r++)
                #pragma unroll
                for (int j = 0; j < 4; j++)
                    accp[r][j] = ffma2(apair[r], bd[j], accp[r][j]);
        }
        __syncthreads();
    }

    float bias[4];
    #pragma unroll
    for (int j = 0; j < 4; j++){
        int col = by * 64 + tx * 4 + j;
        bias[j] = (col < D) ? bl[col] : 0.f;
    }
    #pragma unroll
    for (int r = 0; r < 4; r++){
        int row0 = rowBase + ty * 8 + 2 * r;
        #pragma unroll
        for (int j = 0; j < 4; j++){
            float v0, v1; unpack2(accp[r][j], v0, v1);
            int col = by * 64 + tx * 4 + j;
            if (row0 < NN){
                if (col < D) g_xl[row0 * D + col]     = v0 + bias[j];
                else         g_xr[row0 * D + col - D] = v0;
            }
            if (row0 + 1 < NN){
                if (col < D) g_xl[(row0 + 1) * D + col]     = v1 + bias[j];
                else         g_xr[(row0 + 1) * D + col - D] = v1;
            }
        }
    }
}

// ---------------- fused per-node GATv2: score + online softmax + aggregate + ELU ----
// One warp per destination node. Heads split at lane 16 (H=2).
template<int D, int LAYER>
__global__ void __launch_bounds__(256) k_node(const float* __restrict__ att,
                                              const float* __restrict__ bias)
{
    const int PL = D / 32;                 // columns per lane (2 or 1)
    int gt = blockIdx.x * blockDim.x + threadIdx.x;
    int n = gt >> 5, lane = gt & 31;
    if (n >= NN) return;

    float xr[PL], at[PL], acc[PL];
    #pragma unroll
    for (int p = 0; p < PL; p++){
        int c = lane * PL + p;
        xr[p]  = g_xr[n * D + c];
        at[p]  = att[c];
        acc[p] = 0.f;
    }
    float m0 = -INFINITY, m1 = -INFINITY, l0 = 0.f, l1 = 0.f;
    const bool hi = (lane & 16) != 0;

    const int beg = g_rowptr[n], end = g_rowptr[n + 1];
    const int total = end - beg;

    for (int base = 0; base < total; base += 32){
        int cnt = min(32, total - base);
        int idx = beg + base + lane;
        int sl = (idx < end) ? g_csrc[idx] : 0;

        auto loadrow = [&](int jj, float* dst){
            int s = __shfl_sync(0xFFFFFFFFu, sl, jj);
            if (PL == 2){
                float2 t2 = *(const float2*)&g_xl[s * D + lane * 2];
                dst[0] = t2.x; dst[1] = t2.y;
            } else {
                dst[0] = g_xl[s * D + lane];
            }
        };
        auto scorepart = [&](const float* xv){
            float part = 0.f;
            #pragma unroll
            for (int p = 0; p < PL; p++){
                float v = xv[p] + xr[p];
                v = v > 0.f ? v : 0.2f * v;        // leaky_relu(0.2)
                part += v * at[p];
            }
            return part;
        };
        auto update = [&](float s0, float s1, const float* xv){
            if (s0 > m0){                           // warp-uniform branch
                float c = __expf(m0 - s0);          // exp(-inf)=0 handles first edge
                l0 *= c; m0 = s0;
                float cs = hi ? 1.f : c;
                #pragma unroll
                for (int p = 0; p < PL; p++) acc[p] *= cs;
            }
            if (s1 > m1){
                float c = __expf(m1 - s1);
                l1 *= c; m1 = s1;
                float cs = hi ? c : 1.f;
                #pragma unroll
                for (int p = 0; p < PL; p++) acc[p] *= cs;
            }
            float w0 = __expf(s0 - m0), w1 = __expf(s1 - m1);
            l0 += w0; l1 += w1;
            float ww = hi ? w1 : w0;
            #pragma unroll
            for (int p = 0; p < PL; p++) acc[p] += ww * xv[p];
        };

        float A[PL], B[PL];
        if (cnt > 0) loadrow(0, A);
        if (cnt > 1) loadrow(1, B);

        for (int j = 0; j < cnt; j += 2){
            bool haveB = (j + 1 < cnt);
            float curA[PL], curB[PL];
            #pragma unroll
            for (int p = 0; p < PL; p++){ curA[p] = A[p]; curB[p] = B[p]; }
            if (j + 2 < cnt) loadrow(j + 2, A);     // prefetch next pair
            if (j + 3 < cnt) loadrow(j + 3, B);

            float pA = scorepart(curA);
            float pB = haveB ? scorepart(curB) : 0.f;
            #pragma unroll
            for (int o = 1; o < 16; o <<= 1){
                pA += __shfl_xor_sync(0xFFFFFFFFu, pA, o);
                pB += __shfl_xor_sync(0xFFFFFFFFu, pB, o);
            }
            float sA0 = __shfl_sync(0xFFFFFFFFu, pA, 0);
            float sA1 = __shfl_sync(0xFFFFFFFFu, pA, 16);
            float sB0 = __shfl_sync(0xFFFFFFFFu, pB, 0);
            float sB1 = __shfl_sync(0xFFFFFFFFu, pB, 16);

            update(sA0, sA1, curA);
            if (haveB) update(sB0, sB1, curB);
        }
    }

    float linv = 1.f / (hi ? l1 : l0);             // self-loop => nonempty segment
    if (LAYER == 1){
        float2 o;
        o.x = acc[0] * linv + bias[lane * 2 + 0];
        o.y = (PL == 2) ? acc[PL - 1] * linv + bias[lane * 2 + 1] : 0.f;
        o.x = o.x > 0.f ? o.x : (__expf(o.x) - 1.f);  // ELU
        o.y = o.y > 0.f ? o.y : (__expf(o.y) - 1.f);
        *(float2*)&g_h1[n * D + lane * 2] = o;
    } else {
        int b = g_batch[n];
        float v = acc[0] * linv + bias[lane];
        v = v > 0.f ? v : (__expf(v) - 1.f);
        atomicAdd(&g_pool[b * 32 + lane], v);
        if (lane == 0) atomicAdd(&g_cnt[b], 1.f);
    }
}

// ---------------- fc + log_softmax: one warp per graph ----------------
__global__ void k_head(const float* __restrict__ Wfc, const float* __restrict__ bfc,
                       float* __restrict__ out)
{
    int gt = blockIdx.x * blockDim.x + threadIdx.x;
    int g = gt >> 5, lane = gt & 31;
    if (g >= NG) return;
    float c = g_cnt[g];
    float p = g_pool[g * 32 + lane] / fmaxf(c, 1.f);
    float lg[6];
    #pragma unroll
    for (int j = 0; j < 6; j++) lg[j] = p * Wfc[lane * 6 + j];
    #pragma unroll
    for (int o = 16; o > 0; o >>= 1)
        #pragma unroll
        for (int j = 0; j < 6; j++) lg[j] += __shfl_xor_sync(0xFFFFFFFFu, lg[j], o);
    if (lane == 0){
        float m = -INFINITY;
        #pragma unroll
        for (int j = 0; j < 6; j++){ lg[j] += bfc[j]; m = fmaxf(m, lg[j]); }
        float sum = 0.f;
        #pragma unroll
        for (int j = 0; j < 6; j++) sum += expf(lg[j] - m);
        float lse = m + logf(sum);
        #pragma unroll
        for (int j = 0; j < 6; j++) out[g * 6 + j] = lg[j] - lse;
    }
}

// ---------------- launch ----------------
extern "C" void kernel_launch(void* const* d_in, const int* in_sizes, int n_in,
                              void* d_out, int out_size)
{
    const float* x    = (const float*)d_in[0];
    const void*  ei   = d_in[1];
    const void*  batch= d_in[2];
    const float* Wl1  = (const float*)d_in[3];
    const float* bl1  = (const float*)d_in[4];
    const float* Wr1  = (const float*)d_in[5];
    const float* att1 = (const float*)d_in[6];
    const float* b1   = (const float*)d_in[7];
    const float* Wl2  = (const float*)d_in[8];
    const float* bl2  = (const float*)d_in[9];
    const float* Wr2  = (const float*)d_in[10];
    const float* att2 = (const float*)d_in[11];
    const float* b2   = (const float*)d_in[12];
    const float* Wfc  = (const float*)d_in[13];
    const float* bfc  = (const float*)d_in[14];
    float* out = (float*)d_out;

    const int TB = 256;

    static cudaStream_t s2 = nullptr;
    static cudaEvent_t evFork = nullptr, evJoin = nullptr;
    static int streamsOK = -1;
    if (streamsOK < 0){
        streamsOK = (cudaStreamCreateWithFlags(&s2, cudaStreamNonBlocking) == cudaSuccess &&
                     cudaEventCreateWithFlags(&evFork, cudaEventDisableTiming) == cudaSuccess &&
                     cudaEventCreateWithFlags(&evJoin, cudaEventDisableTiming) == cudaSuccess) ? 1 : 0;
    }

    if (streamsOK){
        // ---- fork: CSR build on s2 concurrent with layer-1 GEMM on main ----
        cudaEventRecord(evFork, 0);
        cudaStreamWaitEvent(s2, evFork, 0);

        k_prep   <<<cdiv(NN, TB),   TB, 0, s2>>>((const unsigned*)ei);
        k_convert<<<cdiv(ETOT, TB), TB, 0, s2>>>(ei, batch);
        k_scan1  <<<NBLK, 256, 0, s2>>>();
        k_scan2  <<<1,    256, 0, s2>>>();
        k_scan3  <<<NBLK, 256, 0, s2>>>();
        k_scatter<<<cdiv(ETOT, TB), TB, 0, s2>>>();
        cudaEventRecord(evJoin, s2);

        k_lin<128, 64><<<dim3(cdiv(NN, 128), 2), TB>>>(x, Wl1, bl1, Wr1);

        // ---- join before first consumer of the CSR ----
        cudaStreamWaitEvent(0, evJoin, 0);
    } else {
        k_prep   <<<cdiv(NN, TB),   TB>>>((const unsigned*)ei);
        k_convert<<<cdiv(ETOT, TB), TB>>>(ei, batch);
        k_scan1  <<<NBLK, 256>>>();
        k_scan2  <<<1,    256>>>();
        k_scan3  <<<NBLK, 256>>>();
        k_scatter<<<cdiv(ETOT, TB), TB>>>();
        k_lin<128, 64><<<dim3(cdiv(NN, 128), 2), TB>>>(x, Wl1, bl1, Wr1);
    }

    // ---- layer 1 attention ----
    k_node<64, 1><<<cdiv(NN * 32, TB), TB>>>(att1, b1);

    // ---- layer 2: 64 -> (2 heads x 16), concat 32 (+ fused mean-pool) ----
    k_lin<64, 32><<<dim3(cdiv(NN, 128), 1), TB>>>(nullptr, Wl2, bl2, Wr2);
    k_node<32, 2><<<cdiv(NN * 32, TB), TB>>>(att2, b2);

    // ---- head ----
    k_head<<<cdiv(NG * 32, TB), TB>>>(Wfc, bfc, out);
}

// round 13
// speedup vs baseline: 1.1417x; 1.1417x over previous
#include <cuda_runtime.h>
#include <math.h>

#define NN 50000
#define NE 800000
#define ETOT 850000   // NE + NN self loops
#define NG 512
#define NBLK ((NN + 255) / 256)   // 196 scan blocks

static inline int cdiv(int a, int b){ return (a + b - 1) / b; }

// ---------------- scratch (device globals; no allocations allowed) ----------------
__device__ __align__(256) float g_xl [NN * 64];   // source transform
__device__ __align__(256) float g_xr [NN * 64];   // target transform
__device__ __align__(256) float g_h1 [NN * 64];   // layer1 output (ELU'd)
__device__ __align__(256) float g_pool[NG * 32];
__device__ __align__(256) float g_cnt [NG];
__device__ __align__(256) int   g_src [ETOT];     // int32 edge sources (incl self loops)
__device__ __align__(256) int   g_dst [ETOT];     // int32 edge destinations
__device__ __align__(256) int   g_batch[NN];      // int32 graph id per node
__device__ __align__(256) int   g_deg [NN];       // per-dst degree
__device__ __align__(256) int   g_rowptr[NN + 1]; // CSR row pointers (by dst)
__device__ __align__(256) int   g_cursor[NN];     // scatter cursors
__device__ __align__(256) int   g_csrc[ETOT];     // CSR-ordered source node ids
__device__ __align__(256) int   g_bsum[NBLK];     // per-block scan sums
__device__ __align__(256) int   g_boff[NBLK];     // exclusive block offsets
__device__ int g_idx64;                           // 1 if input indices are int64

// ---------------- packed f32x2 helpers (Blackwell; ptxas never auto-fuses) ----------
__device__ __forceinline__ unsigned long long ffma2(unsigned long long a,
                                                    unsigned long long b,
                                                    unsigned long long c){
    unsigned long long d;
    asm("fma.rn.f32x2 %0, %1, %2, %3;" : "=l"(d) : "l"(a), "l"(b), "l"(c));
    return d;
}
__device__ __forceinline__ unsigned long long pack2(float x, float y){
    unsigned long long d;
    asm("mov.b64 %0, {%1, %2};" : "=l"(d) : "f"(x), "f"(y));
    return d;
}
__device__ __forceinline__ void unpack2(unsigned long long v, float& x, float& y){
    asm("mov.b64 {%0, %1}, %2;" : "=f"(x), "=f"(y) : "l"(v));
}

// ---------------- zero pass + index dtype detection (fused) ----------------
__global__ void k_prep(const unsigned* __restrict__ eiraw){
    int t = blockIdx.x * blockDim.x + threadIdx.x;
    if (t < NN)      g_deg[t] = 0;
    if (t < NG * 32) g_pool[t] = 0.f;
    if (t < NG)      g_cnt[t]  = 0.f;
    if (t == 0){
        int is64 = 1;
        for (int i = 0; i < 128; i++){
            if (eiraw[2 * i + 1] != 0u) { is64 = 0; break; }
        }
        g_idx64 = is64;
    }
}

// ---------------- convert + histogram (fused single edge pass) ----------------
__global__ void k_convert(const void* __restrict__ ei, const void* __restrict__ batch){
    int t = blockIdx.x * blockDim.x + threadIdx.x;
    int is64 = g_idx64;
    if (t < ETOT){
        int s, d;
        if (t < NE){
            if (is64){
                s = (int)((const long long*)ei)[t];
                d = (int)((const long long*)ei)[NE + t];
            } else {
                s = ((const int*)ei)[t];
                d = ((const int*)ei)[NE + t];
            }
        } else { s = t - NE; d = s; }    // self loops appended
        s = min(max(s, 0), NN - 1);      // memory-safety clamp
        d = min(max(d, 0), NN - 1);
        g_src[t] = s; g_dst[t] = d;
        atomicAdd(&g_deg[d], 1);
    }
    if (t < NN){
        int b = is64 ? (int)((const long long*)batch)[t] : ((const int*)batch)[t];
        g_batch[t] = min(max(b, 0), NG - 1);
    }
}

// ---------------- multi-block exclusive scan of g_deg -> g_rowptr ----------------
__device__ __forceinline__ int blockScanIncl(int v, int tid, int* wsum){
    int x = v;
    #pragma unroll
    for (int o = 1; o < 32; o <<= 1){
        int y = __shfl_up_sync(0xFFFFFFFFu, x, o);
        if ((tid & 31) >= o) x += y;
    }
    if ((tid & 31) == 31) wsum[tid >> 5] = x;
    __syncthreads();
    if (tid < 8){
        int w = wsum[tid];
        #pragma unroll
        for (int o = 1; o < 8; o <<= 1){
            int y = __shfl_up_sync(0xFFu, w, o);
            if (tid >= o) w += y;
        }
        wsum[tid] = w;
    }
    __syncthreads();
    int base = (tid >= 32) ? wsum[(tid >> 5) - 1] : 0;
    return x + base;
}

__global__ void __launch_bounds__(256) k_scan1(){
    __shared__ int wsum[8];
    int tid = threadIdx.x, bid = blockIdx.x;
    int i = bid * 256 + tid;
    int v = (i < NN) ? g_deg[i] : 0;
    int incl = blockScanIncl(v, tid, wsum);
    if (i < NN) g_rowptr[i] = incl - v;         // exclusive within block
    if (tid == 255) g_bsum[bid] = incl;         // block total
}

__global__ void __launch_bounds__(256) k_scan2(){
    __shared__ int wsum[8];
    int tid = threadIdx.x;
    int v = (tid < NBLK) ? g_bsum[tid] : 0;
    int incl = blockScanIncl(v, tid, wsum);
    if (tid < NBLK) g_boff[tid] = incl - v;     // exclusive block offsets
}

__global__ void __launch_bounds__(256) k_scan3(){
    int i = blockIdx.x * 256 + threadIdx.x;
    if (i < NN){
        int val = g_rowptr[i] + g_boff[blockIdx.x];
        g_rowptr[i] = val;
        g_cursor[i] = val;
    }
    if (i == 0) g_rowptr[NN] = ETOT;            // total is statically known
}

__global__ void k_scatter(){
    int e = blockIdx.x * blockDim.x + threadIdx.x;
    if (e >= ETOT) return;
    int d = g_dst[e];
    int pos = atomicAdd(&g_cursor[d], 1);
    g_csrc[pos] = g_src[e];
}

// ---------------- linear: xl = X@Wl + bl ; xr = X@Wr  (fused as one GEMM, N=2D) ----
// BM=128, BN=64, BK=16, 256 threads, 8x4 register tile, double-buffered smem,
// packed fma.rn.f32x2 inner product.
template<int K, int D>
__global__ void __launch_bounds__(256) k_lin(const float* __restrict__ Xin,
                                             const float* __restrict__ Wl,
                                             const float* __restrict__ bl,
                                             const float* __restrict__ Wr)
{
    const float* __restrict__ X = (K == 128) ? Xin : (const float*)g_h1;

    __shared__ float As[2][16][132];   // padded, stored transposed [k][m]
    __shared__ float Bs[2][16][64];

    const int tid = threadIdx.x;
    const int rowBase = blockIdx.x * 128;
    const int by = blockIdx.y;

    const int ra = tid >> 2, ka = (tid & 3) << 2;
    const int rb = tid >> 4, jb = (tid & 15) << 2;
    const int tx = tid & 15, ty = tid >> 4;

    const int jglob = by * 64 + jb;                 // virtual concat [Wl | Wr]
    const float* Wp = (jglob < D) ? Wl : Wr;
    const int jj = (jglob < D) ? jglob : (jglob - D);

    auto loadTile = [&](int k0, int buf){
        #pragma unroll
        for (int h = 0; h < 2; h++){
            int r = ra + h * 64;
            int gr = rowBase + r;
            float4 av = make_float4(0.f, 0.f, 0.f, 0.f);
            if (gr < NN) av = *(const float4*)&X[gr * K + k0 + ka];
            As[buf][ka + 0][r] = av.x; As[buf][ka + 1][r] = av.y;
            As[buf][ka + 2][r] = av.z; As[buf][ka + 3][r] = av.w;
        }
        float4 bv = *(const float4*)&Wp[(k0 + rb) * D + jj];
        *(float4*)&Bs[buf][rb][jb] = bv;
    };

    unsigned long long accp[4][4];
    #pragma unroll
    for (int r = 0; r < 4; r++)
        #pragma unroll
        for (int j = 0; j < 4; j++) accp[r][j] = 0ull;

    loadTile(0, 0);
    __syncthreads();

    int buf = 0;
    for (int k0 = 0; k0 < K; k0 += 16, buf ^= 1){
        if (k0 + 16 < K) loadTile(k0 + 16, buf ^ 1);   // overlap loads with compute

        #pragma unroll
        for (int kk = 0; kk < 16; kk++){
            const ulonglong2* ap = (const ulonglong2*)&As[buf][kk][ty * 8];
            ulonglong2 p01 = ap[0], p23 = ap[1];
            unsigned long long apair[4] = {p01.x, p01.y, p23.x, p23.y};
            float4 b = *(const float4*)&Bs[buf][kk][tx * 4];
            unsigned long long bd[4] = {pack2(b.x, b.x), pack2(b.y, b.y),
                                        pack2(b.z, b.z), pack2(b.w, b.w)};
            #pragma unroll
            for (int r = 0; r < 4; r++)
                #pragma unroll
                for (int j = 0; j < 4; j++)
                    accp[r][j] = ffma2(apair[r], bd[j], accp[r][j]);
        }
        __syncthreads();
    }

    float bias[4];
    #pragma unroll
    for (int j = 0; j < 4; j++){
        int col = by * 64 + tx * 4 + j;
        bias[j] = (col < D) ? bl[col] : 0.f;
    }
    #pragma unroll
    for (int r = 0; r < 4; r++){
        int row0 = rowBase + ty * 8 + 2 * r;
        #pragma unroll
        for (int j = 0; j < 4; j++){
            float v0, v1; unpack2(accp[r][j], v0, v1);
            int col = by * 64 + tx * 4 + j;
            if (row0 < NN){
                if (col < D) g_xl[row0 * D + col]     = v0 + bias[j];
                else         g_xr[row0 * D + col - D] = v0;
            }
            if (row0 + 1 < NN){
                if (col < D) g_xl[(row0 + 1) * D + col]     = v1 + bias[j];
                else         g_xr[(row0 + 1) * D + col - D] = v1;
            }
        }
    }
}

// ---------------- fused per-node GATv2: score + online softmax + aggregate + ELU ----
// One warp per destination node. Heads split at lane 16 (H=2).
// Per-lane softmax state: after the 4-step xor reduce every lane holds its own
// half-warp's head score, and each lane only ever consumes its own head's
// m/l/acc -> no broadcasts, single-branch update.
template<int D, int LAYER>
__global__ void __launch_bounds__(256) k_node(const float* __restrict__ att,
                                              const float* __restrict__ bias)
{
    const int PL = D / 32;                 // columns per lane (2 or 1)
    int gt = blockIdx.x * blockDim.x + threadIdx.x;
    int n = gt >> 5, lane = gt & 31;
    if (n >= NN) return;

    float xr[PL], at[PL], acc[PL];
    #pragma unroll
    for (int p = 0; p < PL; p++){
        int c = lane * PL + p;
        xr[p]  = g_xr[n * D + c];
        at[p]  = att[c];
        acc[p] = 0.f;
    }
    float m = -INFINITY, l = 0.f;          // own-head online softmax state

    const int beg = g_rowptr[n], end = g_rowptr[n + 1];
    const int total = end - beg;

    for (int base = 0; base < total; base += 32){
        int cnt = min(32, total - base);
        int idx = beg + base + lane;
        int sl = (idx < end) ? g_csrc[idx] : 0;

        auto loadrow = [&](int jj, float* dst){
            int s = __shfl_sync(0xFFFFFFFFu, sl, jj);
            if (PL == 2){
                float2 t2 = *(const float2*)&g_xl[s * D + lane * 2];
                dst[0] = t2.x; dst[1] = t2.y;
            } else {
                dst[0] = g_xl[s * D + lane];
            }
        };
        auto scorepart = [&](const float* xv){
            float part = 0.f;
            #pragma unroll
            for (int p = 0; p < PL; p++){
                float v = xv[p] + xr[p];
                v = v > 0.f ? v : 0.2f * v;        // leaky_relu(0.2)
                part += v * at[p];
            }
            return part;
        };
        auto update = [&](float s, const float* xv){
            // s = this edge's score for THIS lane's head (identical within half)
            if (s > m){                            // half-warp-uniform branch
                float c = __expf(m - s);           // exp(-inf)=0 handles first edge
                l *= c; m = s;
                #pragma unroll
                for (int p = 0; p < PL; p++) acc[p] *= c;
            }
            float w = __expf(s - m);
            l += w;
            #pragma unroll
            for (int p = 0; p < PL; p++) acc[p] += w * xv[p];
        };

        float A[PL], B[PL];
        if (cnt > 0) loadrow(0, A);
        if (cnt > 1) loadrow(1, B);

        for (int j = 0; j < cnt; j += 2){
            bool haveB = (j + 1 < cnt);
            float curA[PL], curB[PL];
            #pragma unroll
            for (int p = 0; p < PL; p++){ curA[p] = A[p]; curB[p] = B[p]; }
            if (j + 2 < cnt) loadrow(j + 2, A);     // prefetch next pair
            if (j + 3 < cnt) loadrow(j + 3, B);

            float pA = scorepart(curA);
            float pB = haveB ? scorepart(curB) : 0.f;
            // interleaved 16-lane xor reduce: every lane ends with its own
            // half's (head's) full score
            #pragma unroll
            for (int o = 1; o < 16; o <<= 1){
                pA += __shfl_xor_sync(0xFFFFFFFFu, pA, o);
                pB += __shfl_xor_sync(0xFFFFFFFFu, pB, o);
            }
            update(pA, curA);
            if (haveB) update(pB, curB);
        }
    }

    float linv = 1.f / l;                  // self-loop => nonempty segment
    if (LAYER == 1){
        float2 o;
        o.x = acc[0] * linv + bias[lane * 2 + 0];
        o.y = (PL == 2) ? acc[PL - 1] * linv + bias[lane * 2 + 1] : 0.f;
        o.x = o.x > 0.f ? o.x : (__expf(o.x) - 1.f);  // ELU
        o.y = o.y > 0.f ? o.y : (__expf(o.y) - 1.f);
        *(float2*)&g_h1[n * D + lane * 2] = o;
    } else {
        int b = g_batch[n];
        float v = acc[0] * linv + bias[lane];
        v = v > 0.f ? v : (__expf(v) - 1.f);
        atomicAdd(&g_pool[b * 32 + lane], v);
        if (lane == 0) atomicAdd(&g_cnt[b], 1.f);
    }
}

// ---------------- fc + log_softmax: one warp per graph ----------------
__global__ void k_head(const float* __restrict__ Wfc, const float* __restrict__ bfc,
                       float* __restrict__ out)
{
    int gt = blockIdx.x * blockDim.x + threadIdx.x;
    int g = gt >> 5, lane = gt & 31;
    if (g >= NG) return;
    float c = g_cnt[g];
    float p = g_pool[g * 32 + lane] / fmaxf(c, 1.f);
    float lg[6];
    #pragma unroll
    for (int j = 0; j < 6; j++) lg[j] = p * Wfc[lane * 6 + j];
    #pragma unroll
    for (int o = 16; o > 0; o >>= 1)
        #pragma unroll
        for (int j = 0; j < 6; j++) lg[j] += __shfl_xor_sync(0xFFFFFFFFu, lg[j], o);
    if (lane == 0){
        float m = -INFINITY;
        #pragma unroll
        for (int j = 0; j < 6; j++){ lg[j] += bfc[j]; m = fmaxf(m, lg[j]); }
        float sum = 0.f;
        #pragma unroll
        for (int j = 0; j < 6; j++) sum += expf(lg[j] - m);
        float lse = m + logf(sum);
        #pragma unroll
        for (int j = 0; j < 6; j++) out[g * 6 + j] = lg[j] - lse;
    }
}

// ---------------- launch ----------------
extern "C" void kernel_launch(void* const* d_in, const int* in_sizes, int n_in,
                              void* d_out, int out_size)
{
    const float* x    = (const float*)d_in[0];
    const void*  ei   = d_in[1];
    const void*  batch= d_in[2];
    const float* Wl1  = (const float*)d_in[3];
    const float* bl1  = (const float*)d_in[4];
    const float* Wr1  = (const float*)d_in[5];
    const float* att1 = (const float*)d_in[6];
    const float* b1   = (const float*)d_in[7];
    const float* Wl2  = (const float*)d_in[8];
    const float* bl2  = (const float*)d_in[9];
    const float* Wr2  = (const float*)d_in[10];
    const float* att2 = (const float*)d_in[11];
    const float* b2   = (const float*)d_in[12];
    const float* Wfc  = (const float*)d_in[13];
    const float* bfc  = (const float*)d_in[14];
    float* out = (float*)d_out;

    const int TB = 256;

    static cudaStream_t s2 = nullptr;
    static cudaEvent_t evFork = nullptr, evJoin = nullptr;
    static int streamsOK = -1;
    if (streamsOK < 0){
        streamsOK = (cudaStreamCreateWithFlags(&s2, cudaStreamNonBlocking) == cudaSuccess &&
                     cudaEventCreateWithFlags(&evFork, cudaEventDisableTiming) == cudaSuccess &&
                     cudaEventCreateWithFlags(&evJoin, cudaEventDisableTiming) == cudaSuccess) ? 1 : 0;
    }

    if (streamsOK){
        // ---- fork: CSR build on s2 concurrent with layer-1 GEMM on main ----
        // (lin1 submitted as the 4th launch so ncu's fixed skip profiles it)
        cudaEventRecord(evFork, 0);
        cudaStreamWaitEvent(s2, evFork, 0);

        k_prep   <<<cdiv(NN, TB),   TB, 0, s2>>>((const unsigned*)ei);   // 1
        k_convert<<<cdiv(ETOT, TB), TB, 0, s2>>>(ei, batch);             // 2
        k_scan1  <<<NBLK, 256, 0, s2>>>();                               // 3
        k_lin<128, 64><<<dim3(cdiv(NN, 128), 2), TB>>>(x, Wl1, bl1, Wr1); // 4 (main)
        k_scan2  <<<1,    256, 0, s2>>>();                               // 5
        k_scan3  <<<NBLK, 256, 0, s2>>>();                               // 6
        k_scatter<<<cdiv(ETOT, TB), TB, 0, s2>>>();                      // 7
        cudaEventRecord(evJoin, s2);

        // ---- join before first consumer of the CSR ----
        cudaStreamWaitEvent(0, evJoin, 0);
    } else {
        k_prep   <<<cdiv(NN, TB),   TB>>>((const unsigned*)ei);
        k_convert<<<cdiv(ETOT, TB), TB>>>(ei, batch);
        k_scan1  <<<NBLK, 256>>>();
        k_scan2  <<<1,    256>>>();
        k_scan3  <<<NBLK, 256>>>();
        k_scatter<<<cdiv(ETOT, TB), TB>>>();
        k_lin<128, 64><<<dim3(cdiv(NN, 128), 2), TB>>>(x, Wl1, bl1, Wr1);
    }

    // ---- layer 1 attention ----
    k_node<64, 1><<<cdiv(NN * 32, TB), TB>>>(att1, b1);

    // ---- layer 2: 64 -> (2 heads x 16), concat 32 (+ fused mean-pool) ----
    k_lin<64, 32><<<dim3(cdiv(NN, 128), 1), TB>>>(nullptr, Wl2, bl2, Wr2);
    k_node<32, 2><<<cdiv(NN * 32, TB), TB>>>(att2, b2);

    // ---- head ----
    k_head<<<cdiv(NG * 32, TB), TB>>>(Wfc, bfc, out);
}